// round 15
// baseline (speedup 1.0000x reference)
#include <cuda_runtime.h>
#include <cuda_fp16.h>

typedef unsigned long long ull;

#define PW    768      // padded width/height
#define PAD   128      // border
#define IMGW  512
#define MAGIC 8388608.0f      // 2^23
#define MAGICH 8388607.5f     // 2^23 - 0.5

// fp16 differential quad images, 4x4 BLOCK-TILED:
//   element E(r,c) = (r>>2)*(PW*4) + (c<<2) + (r&3)
//   byte offset   = r*8 + c*32 + (r>>2)*24544
// Texel = (v00, dx | dy, dxy); bilinear: val = (v00 + wr*dy) + wc*(dx + wr*dxy)
// A (normal): rows = image y, cols = image x.  B (transposed): rows = x, cols = y.
__device__ ull g_quadA[PW * PW];
__device__ ull g_quadB[PW * PW];
__device__ unsigned g_ticket;          // dynamic tile scheduler

__device__ __forceinline__ int tile_idx(int r, int c) {
    return (r >> 2) * (PW * 4) + (c << 2) + (r & 3);
}

// ---------------- packed f32x2 helpers ----------------
__device__ __forceinline__ ull f2u(float a, float b) {
    ull r; asm("mov.b64 %0, {%1, %2};" : "=l"(r) : "f"(a), "f"(b)); return r;
}
__device__ __forceinline__ void u2f(ull v, float& a, float& b) {
    asm("mov.b64 {%0, %1}, %2;" : "=f"(a), "=f"(b) : "l"(v));
}
__device__ __forceinline__ ull fma2(ull a, ull b, ull c) {
    ull d; asm("fma.rn.f32x2 %0, %1, %2, %3;" : "=l"(d) : "l"(a), "l"(b), "l"(c)); return d;
}
__device__ __forceinline__ ull add2(ull a, ull b) {
    ull d; asm("add.rn.f32x2 %0, %1, %2;" : "=l"(d) : "l"(a), "l"(b)); return d;
}
__device__ __forceinline__ ull packq(float v00, float v01, float v10, float v11) {
    float dx  = v01 - v00;
    float dy  = v10 - v00;
    float dxy = (v11 - v10) - (v01 - v00);
    __half2 lo = __floats2half2_rn(v00, dx);
    __half2 hi = __floats2half2_rn(dy, dxy);
    unsigned a = *reinterpret_cast<unsigned*>(&lo);
    unsigned b = *reinterpret_cast<unsigned*>(&hi);
    return (ull)a | ((ull)b << 32);
}

__device__ __forceinline__ float ipad(const float* img, int v, int u) {
    int sv = v - PAD, su = u - PAD;
    if (sv < 0 || sv >= IMGW || su < 0 || su >= IMGW) return 0.0f;
    return __ldg(&img[sv * IMGW + su]);
}

// ---------------- ticket reset (graph-capturable, deterministic) ----------------
__global__ void reset_kernel(unsigned start) {
    g_ticket = start;
}

// ---------------- fused prep: both differential quad images (tiled) ----------------
__global__ void prep_kernel(const float* __restrict__ img) {
    __shared__ float S[33][34];            // S[j][i] = Ip(r0+j, c0+i)
    const int r0 = blockIdx.x * 32;
    const int c0 = blockIdx.y * 32;
    const int tx = threadIdx.x;            // 0..31
    const int ty = threadIdx.y;            // 0..7

    for (int j = ty; j < 33; j += 8)
        for (int i = tx; i < 33; i += 32)
            S[j][i] = ipad(img, r0 + j, c0 + i);
    __syncthreads();

    for (int j = ty; j < 32; j += 8) {
        g_quadA[tile_idx(r0 + j, c0 + tx)] =
            packq(S[j][tx], S[j][tx + 1], S[j + 1][tx], S[j + 1][tx + 1]);
        g_quadB[tile_idx(c0 + j, r0 + tx)] =
            packq(S[tx][j], S[tx + 1][j], S[tx][j + 1], S[tx + 1][j + 1]);
    }
}

// ---------------- radon helpers ----------------
__device__ __forceinline__ ull cgen(ull p, ull MAGH2, ull NMAG2, ull NEG1,
                                    unsigned KOFF, unsigned& off) {
    ull t = add2(p, MAGH2);            // MAGIC + floor(col|row)
    ull f = add2(t, NMAG2);            // exact floors as floats
    ull w = fma2(f, NEG1, p);          // fractional weights (wc, wr)
    float tcf, trf; u2f(t, tcf, trf);
    unsigned Ci = (unsigned)__float_as_int(tcf);
    int      Ri = __float_as_int(trf);
    off = (unsigned)Ri * 8u + Ci * 32u + (unsigned)(Ri >> 2) * 24544u + KOFF;
    return w;
}

__device__ __forceinline__ void consume(uint2 q, ull w, float& acc) {
    __half2 A = *reinterpret_cast<__half2*>(&q.x);   // (v00, dx)
    __half2 B = *reinterpret_cast<__half2*>(&q.y);   // (dy, dxy)
    float wc, wr; u2f(w, wc, wr);
    unsigned wr2u;
    asm("cvt.rn.f16x2.f32 %0, %1, %2;" : "=r"(wr2u) : "f"(wr), "f"(wr));
    __half2 wr2 = *reinterpret_cast<__half2*>(&wr2u);
    __half2 mh = __hfma2(wr2, B, A);                 // (m0, md)
    acc += __low2float(mh);
    acc = fmaf(wc, __high2float(mh), acc);
}

// ---------------- main radon kernel ----------------
// Dynamic persistent scheduling: block processes blockIdx.x, then atomically
// fetches further tiles. Warp = 8 detectors x 4 y-lanes; per-stream strict
// y-range trimming; MLP-4 batches + predicated zero-texel epilogue.
__global__ void __launch_bounds__(128, 12) radon_kernel(const float* __restrict__ angles,
                                                        float* __restrict__ out,
                                                        int nTiles) {
    const int lane = threadIdx.x & 31;
    const int warp = threadIdx.x >> 5;
    const int xi   = lane & 7;
    const int yi   = lane >> 3;

    constexpr unsigned BI   = 0x4B000000u;
    constexpr unsigned KOFF = 0u - (BI * 40u + (BI >> 2) * 24544u);

    const ull NEG1  = f2u(-1.0f, -1.0f);
    const ull MAGH2 = f2u(MAGICH, MAGICH);
    const ull NMAG2 = f2u(-MAGIC, -MAGIC);

    __shared__ int s_tile;
    int tile = blockIdx.x;

    while (tile < nTiles) {
        const int a  = tile >> 4;
        const int xc = tile & 15;
        const int x  = xc * 32 + warp * 8 + xi;

        float s, c;
        sincosf(__ldg(&angles[a]), &s, &c);

        const float bx = fmaf((float)x, 2.0f / 512.0f, 1.0f / 512.0f - 1.0f);
        const float Cx = fmaf(256.0f * c, bx, 383.5f - 255.5f * s);
        const float Cy = fmaf(-256.0f * s, bx, 383.5f - 255.5f * c);

        const bool  tr   = fabsf(s) > fabsf(c);
        const float dcol = tr ? c : s;
        const float drow = tr ? s : c;
        const float Ca   = tr ? Cy : Cx;
        const float Cb   = tr ? Cx : Cy;
        const char* gq   = (const char*)(tr ? g_quadB : g_quadA);

        // ---- y-range where samples can touch nonzero texels ----
        float ylo_c, yhi_c;
        if (fabsf(dcol) > 1e-6f) {
            float inv = __frcp_rn(dcol);
            float a0 = (126.0f - Ca) * inv;
            float a1 = (641.0f - Ca) * inv;
            ylo_c = fminf(a0, a1); yhi_c = fmaxf(a0, a1);
        } else { ylo_c = -1.0e9f; yhi_c = 1.0e9f; }
        {
            float invr = __frcp_rn(drow);               // |drow| >= 0.707
            float b0 = (126.0f - Cb) * invr;
            float b1 = (641.0f - Cb) * invr;
            ylo_c = fmaxf(fminf(b0, b1), ylo_c);
            yhi_c = fminf(fmaxf(b0, b1), yhi_c);
        }
        ylo_c = fmaxf(ylo_c, 0.0f);
        yhi_c = fminf(yhi_c, 512.0f);
        int ilo = (int)ylo_c - 1;
        int ihi = (yhi_c > ylo_c) ? ((int)yhi_c + 2) : -100000;
        ilo = __reduce_min_sync(0xFFFFFFFFu, ilo);
        ihi = __reduce_max_sync(0xFFFFFFFFu, ihi);
        if (ilo < 0) ilo = 0;
        if (ihi > 512) ihi = 512;

        const ull S4  = f2u(4.0f * dcol, 4.0f * drow);
        const ull S42 = add2(S4, S4);
        const ull S43 = add2(S42, S4);
        const ull F4  = f2u(4.0f, 4.0f);

        const float y0 = (float)yi;
        float acc = 0.0f;

        #pragma unroll
        for (int k = 0; k < 2; k++) {
            int tl = (ilo - (k << 8) - 3) >> 2;          // arithmetic shift = floor
            if (tl < 0) tl = 0;
            int th = (ihi - (k << 8) + 3) >> 2;
            if (th > 64) th = 64;
            int cnt = th - tl;
            if (cnt <= 0) continue;
            int mainc = cnt & ~3;                        // strict: t stays in [tl, th)

            const float ybase = y0 + (float)((k << 8) + (tl << 2));
            const ull C = f2u(fmaf(ybase, dcol, Ca), fmaf(ybase, drow, Cb));

            ull t2 = f2u(0.0f, 0.0f);

            #pragma unroll 1
            for (int i = 0; i < mainc; i += 4) {
                ull P  = fma2(t2, S4, C);
                ull p1 = add2(P, S4);
                ull p2 = add2(P, S42);
                ull p3 = add2(P, S43);
                unsigned o0, o1, o2, o3;
                ull w0 = cgen(P,  MAGH2, NMAG2, NEG1, KOFF, o0);
                ull w1 = cgen(p1, MAGH2, NMAG2, NEG1, KOFF, o1);
                ull w2 = cgen(p2, MAGH2, NMAG2, NEG1, KOFF, o2);
                ull w3 = cgen(p3, MAGH2, NMAG2, NEG1, KOFF, o3);

                uint2 q0 = __ldg(reinterpret_cast<const uint2*>(gq + o0));
                uint2 q1 = __ldg(reinterpret_cast<const uint2*>(gq + o1));
                uint2 q2 = __ldg(reinterpret_cast<const uint2*>(gq + o2));
                uint2 q3 = __ldg(reinterpret_cast<const uint2*>(gq + o3));

                consume(q0, w0, acc);
                consume(q1, w1, acc);
                consume(q2, w2, acc);
                consume(q3, w3, acc);

                t2 = add2(t2, F4);
            }

            int rem = cnt - mainc;                       // 0..3
            if (rem > 0) {
                // predicated epilogue: invalid samples load texel (0,0) == 0.0
                ull P  = fma2(t2, S4, C);
                ull p1 = add2(P, S4);
                ull p2 = add2(P, S42);
                unsigned o0, o1, o2;
                ull w0 = cgen(P,  MAGH2, NMAG2, NEG1, KOFF, o0);
                ull w1 = cgen(p1, MAGH2, NMAG2, NEG1, KOFF, o1);
                ull w2 = cgen(p2, MAGH2, NMAG2, NEG1, KOFF, o2);
                o1 = (rem > 1) ? o1 : 0u;
                o2 = (rem > 2) ? o2 : 0u;

                uint2 q0 = __ldg(reinterpret_cast<const uint2*>(gq + o0));
                uint2 q1 = __ldg(reinterpret_cast<const uint2*>(gq + o1));
                uint2 q2 = __ldg(reinterpret_cast<const uint2*>(gq + o2));

                consume(q0, w0, acc);
                consume(q1, w1, acc);
                consume(q2, w2, acc);
            }
        }

        float v = acc;
        v += __shfl_xor_sync(0xFFFFFFFFu, v, 8);
        v += __shfl_xor_sync(0xFFFFFFFFu, v, 16);
        if (yi == 0)
            out[a * IMGW + x] = v;

        // ---- fetch next tile (dynamic scheduling) ----
        __syncthreads();
        if (threadIdx.x == 0)
            s_tile = (int)atomicAdd(&g_ticket, 1u);
        __syncthreads();
        tile = s_tile;
    }
}

extern "C" void kernel_launch(void* const* d_in, const int* in_sizes, int n_in,
                              void* d_out, int out_size) {
    const float* data   = (const float*)d_in[0];
    const float* angles = (const float*)d_in[1];
    if (n_in >= 2 && in_sizes[0] < in_sizes[1]) {
        const float* t = data; data = angles; angles = t;
    }
    int nA = (in_sizes[0] < in_sizes[1]) ? in_sizes[0] : in_sizes[1];

    float* out = (float*)d_out;

    dim3 pgrid(PW / 32, PW / 32);
    prep_kernel<<<pgrid, dim3(32, 8)>>>(data);

    int nTiles = nA * (IMGW / 32);
    int grid = 152 * 12;               // persistent: 12 blocks per SM
    if (grid > nTiles) grid = nTiles;

    reset_kernel<<<1, 1>>>((unsigned)grid);
    radon_kernel<<<grid, 128>>>(angles, out, nTiles);
}

// round 16
// speedup vs baseline: 1.4895x; 1.4895x over previous
#include <cuda_runtime.h>
#include <cuda_fp16.h>

typedef unsigned long long ull;

#define PW    768      // padded width/height
#define PAD   128      // border
#define IMGW  512
#define MAGIC 8388608.0f      // 2^23
#define MAGICH 8388607.5f     // 2^23 - 0.5

// fp16 differential quad images, 4x4 BLOCK-TILED:
//   element E(r,c) = (r>>2)*(PW*4) + (c<<2) + (r&3)
//   byte offset   = r*8 + c*32 + (r>>2)*24544
// Texel = (v00, dx | dy, dxy); bilinear: val = (v00 + wr*dy) + wc*(dx + wr*dxy)
// A (normal): rows = image y, cols = image x.  B (transposed): rows = x, cols = y.
__device__ ull g_quadA[PW * PW];
__device__ ull g_quadB[PW * PW];

__device__ __forceinline__ int tile_idx(int r, int c) {
    return (r >> 2) * (PW * 4) + (c << 2) + (r & 3);
}

// ---------------- packed f32x2 helpers ----------------
__device__ __forceinline__ ull f2u(float a, float b) {
    ull r; asm("mov.b64 %0, {%1, %2};" : "=l"(r) : "f"(a), "f"(b)); return r;
}
__device__ __forceinline__ void u2f(ull v, float& a, float& b) {
    asm("mov.b64 {%0, %1}, %2;" : "=f"(a), "=f"(b) : "l"(v));
}
__device__ __forceinline__ ull fma2(ull a, ull b, ull c) {
    ull d; asm("fma.rn.f32x2 %0, %1, %2, %3;" : "=l"(d) : "l"(a), "l"(b), "l"(c)); return d;
}
__device__ __forceinline__ ull add2(ull a, ull b) {
    ull d; asm("add.rn.f32x2 %0, %1, %2;" : "=l"(d) : "l"(a), "l"(b)); return d;
}
__device__ __forceinline__ ull packq(float v00, float v01, float v10, float v11) {
    float dx  = v01 - v00;
    float dy  = v10 - v00;
    float dxy = (v11 - v10) - (v01 - v00);
    __half2 lo = __floats2half2_rn(v00, dx);
    __half2 hi = __floats2half2_rn(dy, dxy);
    unsigned a = *reinterpret_cast<unsigned*>(&lo);
    unsigned b = *reinterpret_cast<unsigned*>(&hi);
    return (ull)a | ((ull)b << 32);
}

__device__ __forceinline__ float ipad(const float* img, int v, int u) {
    int sv = v - PAD, su = u - PAD;
    if (sv < 0 || sv >= IMGW || su < 0 || su >= IMGW) return 0.0f;
    return __ldg(&img[sv * IMGW + su]);
}

// ---------------- fused prep: 16x16 tiles, one QA + one QB texel per thread ----------------
__global__ void prep_kernel(const float* __restrict__ img) {
    __shared__ float S[17][18];            // S[j][i] = Ip(r0+j, c0+i)
    const int r0 = blockIdx.x * 16;
    const int c0 = blockIdx.y * 16;
    const int tx = threadIdx.x;            // 0..15
    const int ty = threadIdx.y;            // 0..15

    for (int j = ty; j < 17; j += 16)
        for (int i = tx; i < 17; i += 16)
            S[j][i] = ipad(img, r0 + j, c0 + i);
    __syncthreads();

    // QA rows = image y
    g_quadA[tile_idx(r0 + ty, c0 + tx)] =
        packq(S[ty][tx], S[ty][tx + 1], S[ty + 1][tx], S[ty + 1][tx + 1]);
    // QB rows = image x (transposed)
    g_quadB[tile_idx(c0 + ty, r0 + tx)] =
        packq(S[tx][ty], S[tx + 1][ty], S[tx][ty + 1], S[tx + 1][ty + 1]);
}

// ---------------- radon helpers ----------------
__device__ __forceinline__ ull cgen(ull p, ull MAGH2, ull NMAG2, ull NEG1,
                                    unsigned KOFF, unsigned& off) {
    ull t = add2(p, MAGH2);            // MAGIC + floor(col|row)
    ull f = add2(t, NMAG2);            // exact floors as floats
    ull w = fma2(f, NEG1, p);          // fractional weights (wc, wr)
    float tcf, trf; u2f(t, tcf, trf);
    unsigned Ci = (unsigned)__float_as_int(tcf);
    int      Ri = __float_as_int(trf);
    off = (unsigned)Ri * 8u + Ci * 32u + (unsigned)(Ri >> 2) * 24544u + KOFF;
    return w;
}

__device__ __forceinline__ void consume(uint2 q, ull w, float& acc) {
    __half2 A = *reinterpret_cast<__half2*>(&q.x);   // (v00, dx)
    __half2 B = *reinterpret_cast<__half2*>(&q.y);   // (dy, dxy)
    float wc, wr; u2f(w, wc, wr);
    unsigned wr2u;
    asm("cvt.rn.f16x2.f32 %0, %1, %2;" : "=r"(wr2u) : "f"(wr), "f"(wr));
    __half2 wr2 = *reinterpret_cast<__half2*>(&wr2u);
    __half2 mh = __hfma2(wr2, B, A);                 // (m0, md)
    acc += __low2float(mh);
    acc = fmaf(wc, __high2float(mh), acc);
}

// ---------------- main radon kernel ----------------
// Static persistent grid-stride over tiles (tile = angle*16 + xchunk).
// Warp = 8 detectors x 4 y-lanes; per-stream strict y-range trimming;
// MLP-4 batches + predicated zero-texel epilogue.
__global__ void __launch_bounds__(128, 12) radon_kernel(const float* __restrict__ angles,
                                                        float* __restrict__ out,
                                                        int nTiles) {
    const int lane = threadIdx.x & 31;
    const int warp = threadIdx.x >> 5;
    const int xi   = lane & 7;
    const int yi   = lane >> 3;

    constexpr unsigned BI   = 0x4B000000u;
    constexpr unsigned KOFF = 0u - (BI * 40u + (BI >> 2) * 24544u);

    const ull NEG1  = f2u(-1.0f, -1.0f);
    const ull MAGH2 = f2u(MAGICH, MAGICH);
    const ull NMAG2 = f2u(-MAGIC, -MAGIC);

    for (int tile = blockIdx.x; tile < nTiles; tile += gridDim.x) {
        const int a  = tile >> 4;
        const int xc = tile & 15;
        const int x  = xc * 32 + warp * 8 + xi;

        float s, c;
        sincosf(__ldg(&angles[a]), &s, &c);

        const float bx = fmaf((float)x, 2.0f / 512.0f, 1.0f / 512.0f - 1.0f);
        const float Cx = fmaf(256.0f * c, bx, 383.5f - 255.5f * s);
        const float Cy = fmaf(-256.0f * s, bx, 383.5f - 255.5f * c);

        const bool  tr   = fabsf(s) > fabsf(c);
        const float dcol = tr ? c : s;
        const float drow = tr ? s : c;
        const float Ca   = tr ? Cy : Cx;
        const float Cb   = tr ? Cx : Cy;
        const char* gq   = (const char*)(tr ? g_quadB : g_quadA);

        // ---- y-range where samples can touch nonzero texels ----
        float ylo_c, yhi_c;
        if (fabsf(dcol) > 1e-6f) {
            float inv = __frcp_rn(dcol);
            float a0 = (126.0f - Ca) * inv;
            float a1 = (641.0f - Ca) * inv;
            ylo_c = fminf(a0, a1); yhi_c = fmaxf(a0, a1);
        } else { ylo_c = -1.0e9f; yhi_c = 1.0e9f; }
        {
            float invr = __frcp_rn(drow);               // |drow| >= 0.707
            float b0 = (126.0f - Cb) * invr;
            float b1 = (641.0f - Cb) * invr;
            ylo_c = fmaxf(fminf(b0, b1), ylo_c);
            yhi_c = fminf(fmaxf(b0, b1), yhi_c);
        }
        ylo_c = fmaxf(ylo_c, 0.0f);
        yhi_c = fminf(yhi_c, 512.0f);
        int ilo = (int)ylo_c - 1;
        int ihi = (yhi_c > ylo_c) ? ((int)yhi_c + 2) : -100000;
        ilo = __reduce_min_sync(0xFFFFFFFFu, ilo);
        ihi = __reduce_max_sync(0xFFFFFFFFu, ihi);
        if (ilo < 0) ilo = 0;
        if (ihi > 512) ihi = 512;

        const ull S4  = f2u(4.0f * dcol, 4.0f * drow);
        const ull S42 = add2(S4, S4);
        const ull S43 = add2(S42, S4);
        const ull F4  = f2u(4.0f, 4.0f);

        const float y0 = (float)yi;
        float acc = 0.0f;

        #pragma unroll
        for (int k = 0; k < 2; k++) {
            int tl = (ilo - (k << 8) - 3) >> 2;          // arithmetic shift = floor
            if (tl < 0) tl = 0;
            int th = (ihi - (k << 8) + 3) >> 2;
            if (th > 64) th = 64;
            int cnt = th - tl;
            if (cnt <= 0) continue;
            int mainc = cnt & ~3;                        // strict: t stays in [tl, th)

            const float ybase = y0 + (float)((k << 8) + (tl << 2));
            const ull C = f2u(fmaf(ybase, dcol, Ca), fmaf(ybase, drow, Cb));

            ull t2 = f2u(0.0f, 0.0f);

            #pragma unroll 1
            for (int i = 0; i < mainc; i += 4) {
                ull P  = fma2(t2, S4, C);
                ull p1 = add2(P, S4);
                ull p2 = add2(P, S42);
                ull p3 = add2(P, S43);
                unsigned o0, o1, o2, o3;
                ull w0 = cgen(P,  MAGH2, NMAG2, NEG1, KOFF, o0);
                ull w1 = cgen(p1, MAGH2, NMAG2, NEG1, KOFF, o1);
                ull w2 = cgen(p2, MAGH2, NMAG2, NEG1, KOFF, o2);
                ull w3 = cgen(p3, MAGH2, NMAG2, NEG1, KOFF, o3);

                uint2 q0 = __ldg(reinterpret_cast<const uint2*>(gq + o0));
                uint2 q1 = __ldg(reinterpret_cast<const uint2*>(gq + o1));
                uint2 q2 = __ldg(reinterpret_cast<const uint2*>(gq + o2));
                uint2 q3 = __ldg(reinterpret_cast<const uint2*>(gq + o3));

                consume(q0, w0, acc);
                consume(q1, w1, acc);
                consume(q2, w2, acc);
                consume(q3, w3, acc);

                t2 = add2(t2, F4);
            }

            int rem = cnt - mainc;                       // 0..3
            if (rem > 0) {
                // predicated epilogue: invalid samples load texel (0,0) == 0.0
                ull P  = fma2(t2, S4, C);
                ull p1 = add2(P, S4);
                ull p2 = add2(P, S42);
                unsigned o0, o1, o2;
                ull w0 = cgen(P,  MAGH2, NMAG2, NEG1, KOFF, o0);
                ull w1 = cgen(p1, MAGH2, NMAG2, NEG1, KOFF, o1);
                ull w2 = cgen(p2, MAGH2, NMAG2, NEG1, KOFF, o2);
                o1 = (rem > 1) ? o1 : 0u;
                o2 = (rem > 2) ? o2 : 0u;

                uint2 q0 = __ldg(reinterpret_cast<const uint2*>(gq + o0));
                uint2 q1 = __ldg(reinterpret_cast<const uint2*>(gq + o1));
                uint2 q2 = __ldg(reinterpret_cast<const uint2*>(gq + o2));

                consume(q0, w0, acc);
                consume(q1, w1, acc);
                consume(q2, w2, acc);
            }
        }

        float v = acc;
        v += __shfl_xor_sync(0xFFFFFFFFu, v, 8);
        v += __shfl_xor_sync(0xFFFFFFFFu, v, 16);
        if (yi == 0)
            out[a * IMGW + x] = v;
    }
}

extern "C" void kernel_launch(void* const* d_in, const int* in_sizes, int n_in,
                              void* d_out, int out_size) {
    const float* data   = (const float*)d_in[0];
    const float* angles = (const float*)d_in[1];
    if (n_in >= 2 && in_sizes[0] < in_sizes[1]) {
        const float* t = data; data = angles; angles = t;
    }
    int nA = (in_sizes[0] < in_sizes[1]) ? in_sizes[0] : in_sizes[1];

    float* out = (float*)d_out;

    dim3 pgrid(PW / 16, PW / 16);      // 48 x 48 = 2304 blocks
    prep_kernel<<<pgrid, dim3(16, 16)>>>(data);

    int nTiles = nA * (IMGW / 32);
    // all blocks resident (occ 12 -> 1824 max); ~3 strided tiles per block
    int grid = (nTiles + 2) / 3;
    if (grid > 1824) grid = 1824;
    if (grid > nTiles) grid = nTiles;
    radon_kernel<<<grid, 128>>>(angles, out, nTiles);
}